// round 2
// baseline (speedup 1.0000x reference)
#include <cuda_runtime.h>
#include <math.h>

#define B_   8
#define H_   64
#define W_   64
#define C_   256
#define CI_  128
#define NQ_  (H_*W_)        // 4096
#define NS_  (H_*(W_/2))    // 2048
#define M_   (B_*NQ_)       // 32768
#define MS_  (B_*NS_)       // 16384
#define EPS_ 1e-3f

// ---- scratch (static __device__ — allocation-free per harness rules) ----
__device__ float d_x[M_*(size_t)C_];      // elu(bn1(inputs))          33.5 MB
__device__ float d_theta[M_*(size_t)CI_]; // theta projection          16.8 MB
__device__ float d_g[MS_*(size_t)CI_];    // pooled g projection        8.4 MB
__device__ float d_phi[MS_*(size_t)CI_];  // pooled phi projection      8.4 MB
__device__ float d_y[M_*(size_t)CI_];     // attention output          16.8 MB

// =====================================================================
// K1: x = elu(bn1(inputs))   (vectorized float4, channel = last axis)
// =====================================================================
__global__ void bn1_elu_kernel(const float* __restrict__ in,
                               const float* __restrict__ gamma,
                               const float* __restrict__ beta,
                               const float* __restrict__ mean,
                               const float* __restrict__ var) {
    int i = blockIdx.x * blockDim.x + threadIdx.x;      // float4 index
    int c0 = (i & (C_/4 - 1)) * 4;
    float4 v = ((const float4*)in)[i];
    float r[4] = {v.x, v.y, v.z, v.w};
#pragma unroll
    for (int j = 0; j < 4; j++) {
        int c = c0 + j;
        float sc = gamma[c] * rsqrtf(var[c] + EPS_);
        float t = (r[j] - mean[c]) * sc + beta[c];
        r[j] = t > 0.f ? t : expm1f(t);
    }
    ((float4*)d_x)[i] = make_float4(r[0], r[1], r[2], r[3]);
}

// =====================================================================
// K2: projection GEMM  out[M,128] = d_x[M,256] @ W[256,128] + b
//     blockIdx.y: 0 -> theta (plain), 1 -> g (pooled), 2 -> phi (pooled)
//     Pooling (max over width pairs) fused into epilogue: pairs are
//     consecutive M rows, fully contained in each thread's 8-row tile.
// =====================================================================
__global__ void __launch_bounds__(256) proj_gemm_kernel(
        const float* __restrict__ W0, const float* __restrict__ b0,
        const float* __restrict__ W1, const float* __restrict__ b1,
        const float* __restrict__ W2, const float* __restrict__ b2) {
    __shared__ float As[16][132];
    __shared__ float Bs[16][132];
    const int which = blockIdx.y;
    const float* Wt   = (which == 0) ? W0 : (which == 1) ? W1 : W2;
    const float* bias = (which == 0) ? b0 : (which == 1) ? b1 : b2;
    const int bm = blockIdx.x * 128;
    const int t = threadIdx.x;
    const int tm = t >> 4, tn = t & 15;
    float acc[8][8] = {};

    for (int k0 = 0; k0 < C_; k0 += 16) {
#pragma unroll
        for (int r = 0; r < 2; r++) {
            int idx = t + r * 256;                 // 0..511 float4 slots
            int row = idx >> 2;                    // 128 rows x 4 float4
            int kk  = (idx & 3) << 2;
            float4 v = *(const float4*)(d_x + (size_t)(bm + row) * C_ + k0 + kk);
            As[kk+0][row] = v.x; As[kk+1][row] = v.y;
            As[kk+2][row] = v.z; As[kk+3][row] = v.w;
            int kk2 = idx >> 5;                    // 16 k-rows x 32 float4
            int nn  = (idx & 31) << 2;
            *(float4*)&Bs[kk2][nn] =
                *(const float4*)(Wt + (size_t)(k0 + kk2) * CI_ + nn);
        }
        __syncthreads();
#pragma unroll
        for (int k = 0; k < 16; k++) {
            float a[8], bb[8];
            *(float4*)(a)    = *(float4*)&As[k][tm*8];
            *(float4*)(a+4)  = *(float4*)&As[k][tm*8+4];
            *(float4*)(bb)   = *(float4*)&Bs[k][tn*8];
            *(float4*)(bb+4) = *(float4*)&Bs[k][tn*8+4];
#pragma unroll
            for (int i = 0; i < 8; i++)
#pragma unroll
                for (int j = 0; j < 8; j++) acc[i][j] += a[i] * bb[j];
        }
        __syncthreads();
    }

    float* outp = (which == 0) ? d_theta : (which == 1) ? d_g : d_phi;
    float bz[8];
#pragma unroll
    for (int j = 0; j < 8; j++) bz[j] = bias[tn*8 + j];

    if (which == 0) {
#pragma unroll
        for (int i = 0; i < 8; i++) {
            size_t m = bm + tm*8 + i;
            float4 o0 = make_float4(acc[i][0]+bz[0], acc[i][1]+bz[1],
                                    acc[i][2]+bz[2], acc[i][3]+bz[3]);
            float4 o1 = make_float4(acc[i][4]+bz[4], acc[i][5]+bz[5],
                                    acc[i][6]+bz[6], acc[i][7]+bz[7]);
            *(float4*)(outp + m*CI_ + tn*8)     = o0;
            *(float4*)(outp + m*CI_ + tn*8 + 4) = o1;
        }
    } else {
#pragma unroll
        for (int i = 0; i < 8; i += 2) {
            size_t pm = (size_t)(bm + tm*8 + i) >> 1;
            float o[8];
#pragma unroll
            for (int j = 0; j < 8; j++)
                o[j] = fmaxf(acc[i][j], acc[i+1][j]) + bz[j];
            *(float4*)(outp + pm*CI_ + tn*8)     = make_float4(o[0],o[1],o[2],o[3]);
            *(float4*)(outp + pm*CI_ + tn*8 + 4) = make_float4(o[4],o[5],o[6],o[7]);
        }
    }
}

// =====================================================================
// K3: flash-attention:  y = softmax(theta @ phi^T) @ g
//     Block = (batch, 64-query tile). Online softmax, O in registers.
//     SMEM: theta^T[128][68], phi^T[128][68], g[64][132], P[64][68],
//           reduction scratch.  ~125.7 KB dynamic.
// =====================================================================
#define ATT_SMEM_FLOATS (128*68 + 128*68 + 64*132 + 64*68 + 64*16 + 64*3)
#define ATT_SMEM_BYTES  (ATT_SMEM_FLOATS * 4)

__global__ void __launch_bounds__(256) attn_kernel() {
    extern __shared__ float sm_[];
    float* sTh    = sm_;                  // [128][68] k-major theta
    float* sPh    = sTh + 128*68;         // [128][68] k-major phi chunk
    float* sG     = sPh + 128*68;         // [64][132] g chunk
    float* sP     = sG  + 64*132;         // [64][68]  probabilities
    float* sRed   = sP  + 64*68;          // [64][16]  partial max/sum
    float* sM     = sRed + 64*16;         // [64] running max
    float* sScale = sM + 64;              // [64] exp(m_old - m_new)
    float* sL     = sScale + 64;          // [64] running denom

    const int b  = blockIdx.y;
    const int q0 = blockIdx.x * 64;
    const int t  = threadIdx.x;
    const int ty = t >> 4, tx = t & 15;

    const float* thp = d_theta + ((size_t)b * NQ_ + q0) * CI_;
    const float* php = d_phi   + (size_t)b * NS_ * CI_;
    const float* gp  = d_g     + (size_t)b * NS_ * CI_;

    // load theta tile transposed (k-major)
    {
        const int row = t >> 2, part = t & 3;
        const float* src = thp + (size_t)row * CI_ + part * 32;
#pragma unroll
        for (int u = 0; u < 8; u++) {
            float4 v = *(const float4*)(src + u * 4);
            int k = part * 32 + u * 4;
            sTh[(k+0)*68+row] = v.x; sTh[(k+1)*68+row] = v.y;
            sTh[(k+2)*68+row] = v.z; sTh[(k+3)*68+row] = v.w;
        }
    }
    if (t < 64) { sM[t] = -1e30f; sL[t] = 0.f; }

    float O[4][8] = {};

    for (int c0 = 0; c0 < NS_; c0 += 64) {
        // load phi chunk (transposed) + g chunk (direct)
        {
            const int row = t >> 2, part = t & 3;
            const float* ps = php + (size_t)(c0 + row) * CI_ + part * 32;
            const float* gs = gp  + (size_t)(c0 + row) * CI_ + part * 32;
#pragma unroll
            for (int u = 0; u < 8; u++) {
                float4 v = *(const float4*)(ps + u * 4);
                int k = part * 32 + u * 4;
                sPh[(k+0)*68+row] = v.x; sPh[(k+1)*68+row] = v.y;
                sPh[(k+2)*68+row] = v.z; sPh[(k+3)*68+row] = v.w;
                *(float4*)&sG[row*132 + part*32 + u*4] = *(const float4*)(gs + u*4);
            }
        }
        __syncthreads();

        // S = theta @ phi^T   (each thread: 4q x 4j)
        float s[4][4] = {};
#pragma unroll 8
        for (int k = 0; k < CI_; k++) {
            float4 a = *(float4*)&sTh[k*68 + ty*4];
            float4 p = *(float4*)&sPh[k*68 + tx*4];
            float av[4] = {a.x, a.y, a.z, a.w};
            float pv[4] = {p.x, p.y, p.z, p.w};
#pragma unroll
            for (int i = 0; i < 4; i++)
#pragma unroll
                for (int j = 0; j < 4; j++) s[i][j] += av[i] * pv[j];
        }
        // per-thread row maxima
#pragma unroll
        for (int i = 0; i < 4; i++) {
            float mx = fmaxf(fmaxf(s[i][0], s[i][1]), fmaxf(s[i][2], s[i][3]));
            sRed[(ty*4+i)*16 + tx] = mx;
        }
        __syncthreads();
        if (t < 64) {
            float mo = sM[t], mn = mo;
#pragma unroll
            for (int i = 0; i < 16; i++) mn = fmaxf(mn, sRed[t*16 + i]);
            sM[t] = mn;
            sScale[t] = __expf(mo - mn);
        }
        __syncthreads();
        // P = exp(S - m), partial row sums, rescale O
#pragma unroll
        for (int i = 0; i < 4; i++) {
            int q = ty*4 + i;
            float mn = sM[q];
            float sc = sScale[q];
            float4 p;
            p.x = __expf(s[i][0] - mn); p.y = __expf(s[i][1] - mn);
            p.z = __expf(s[i][2] - mn); p.w = __expf(s[i][3] - mn);
            *(float4*)&sP[q*68 + tx*4] = p;
            sRed[q*16 + tx] = p.x + p.y + p.z + p.w;
#pragma unroll
            for (int j = 0; j < 8; j++) O[i][j] *= sc;
        }
        __syncthreads();
        if (t < 64) {
            float sum = 0.f;
#pragma unroll
            for (int i = 0; i < 16; i++) sum += sRed[t*16 + i];
            sL[t] = sL[t] * sScale[t] + sum;
        }
        // O += P @ g   (each thread: 4q x 8c)
#pragma unroll 1
        for (int j0 = 0; j0 < 64; j0 += 4) {
            float pr[4][4];
#pragma unroll
            for (int i = 0; i < 4; i++) {
                float4 pv = *(float4*)&sP[(ty*4+i)*68 + j0];
                pr[i][0] = pv.x; pr[i][1] = pv.y; pr[i][2] = pv.z; pr[i][3] = pv.w;
            }
#pragma unroll
            for (int jj = 0; jj < 4; jj++) {
                float4 g0 = *(float4*)&sG[(j0+jj)*132 + tx*8];
                float4 g1 = *(float4*)&sG[(j0+jj)*132 + tx*8 + 4];
                float gv[8] = {g0.x,g0.y,g0.z,g0.w,g1.x,g1.y,g1.z,g1.w};
#pragma unroll
                for (int i = 0; i < 4; i++) {
                    float p = pr[i][jj];
#pragma unroll
                    for (int c = 0; c < 8; c++) O[i][c] += p * gv[c];
                }
            }
        }
        __syncthreads();
    }

    // epilogue: normalize and store y
#pragma unroll
    for (int i = 0; i < 4; i++) {
        int q = ty*4 + i;
        float inv = 1.0f / sL[q];
        float* dst = d_y + ((size_t)b * NQ_ + q0 + q) * CI_ + tx*8;
        *(float4*)dst       = make_float4(O[i][0]*inv, O[i][1]*inv, O[i][2]*inv, O[i][3]*inv);
        *(float4*)(dst + 4) = make_float4(O[i][4]*inv, O[i][5]*inv, O[i][6]*inv, O[i][7]*inv);
    }
}

// =====================================================================
// K4: out = (elu(bn2(y)) @ W_z + b_z) * sita + inputs
//     bn2+elu fused into A-tile load; residual+scale in epilogue.
// =====================================================================
__global__ void __launch_bounds__(256) final_gemm_kernel(
        const float* __restrict__ Wz, const float* __restrict__ bzv,
        const float* __restrict__ g2, const float* __restrict__ b2,
        const float* __restrict__ m2, const float* __restrict__ v2,
        const float* __restrict__ sita, const float* __restrict__ inp,
        float* __restrict__ out) {
    __shared__ float As[16][132];
    __shared__ float Bs[16][132];
    __shared__ float bnS[CI_], bnB[CI_];
    const int t = threadIdx.x;
    if (t < CI_) {
        float sc = g2[t] * rsqrtf(v2[t] + EPS_);
        bnS[t] = sc;
        bnB[t] = b2[t] - m2[t] * sc;
    }
    __syncthreads();

    const int bm = blockIdx.x * 128;
    const int bn = blockIdx.y * 128;
    const int tm = t >> 4, tn = t & 15;
    float acc[8][8] = {};

    for (int k0 = 0; k0 < CI_; k0 += 16) {
#pragma unroll
        for (int r = 0; r < 2; r++) {
            int idx = t + r * 256;
            int row = idx >> 2;
            int kk  = (idx & 3) << 2;
            float4 v = *(const float4*)(d_y + (size_t)(bm + row) * CI_ + k0 + kk);
            float e[4] = {v.x, v.y, v.z, v.w};
#pragma unroll
            for (int j = 0; j < 4; j++) {
                int k = k0 + kk + j;
                float u = e[j] * bnS[k] + bnB[k];
                e[j] = u > 0.f ? u : expm1f(u);
            }
            As[kk+0][row] = e[0]; As[kk+1][row] = e[1];
            As[kk+2][row] = e[2]; As[kk+3][row] = e[3];
            int kk2 = idx >> 5;
            int nn  = (idx & 31) << 2;
            *(float4*)&Bs[kk2][nn] =
                *(const float4*)(Wz + (size_t)(k0 + kk2) * C_ + bn + nn);
        }
        __syncthreads();
#pragma unroll
        for (int k = 0; k < 16; k++) {
            float a[8], bb[8];
            *(float4*)(a)    = *(float4*)&As[k][tm*8];
            *(float4*)(a+4)  = *(float4*)&As[k][tm*8+4];
            *(float4*)(bb)   = *(float4*)&Bs[k][tn*8];
            *(float4*)(bb+4) = *(float4*)&Bs[k][tn*8+4];
#pragma unroll
            for (int i = 0; i < 8; i++)
#pragma unroll
                for (int j = 0; j < 8; j++) acc[i][j] += a[i] * bb[j];
        }
        __syncthreads();
    }

    const float sv = sita[0];
    float bz[8];
#pragma unroll
    for (int j = 0; j < 8; j++) bz[j] = bzv[bn + tn*8 + j];
#pragma unroll
    for (int i = 0; i < 8; i++) {
        size_t m = bm + tm*8 + i;
        size_t n = bn + tn*8;
        float4 iA = *(const float4*)(inp + m * C_ + n);
        float4 iB = *(const float4*)(inp + m * C_ + n + 4);
        float4 o0, o1;
        o0.x = (acc[i][0]+bz[0])*sv + iA.x; o0.y = (acc[i][1]+bz[1])*sv + iA.y;
        o0.z = (acc[i][2]+bz[2])*sv + iA.z; o0.w = (acc[i][3]+bz[3])*sv + iA.w;
        o1.x = (acc[i][4]+bz[4])*sv + iB.x; o1.y = (acc[i][5]+bz[5])*sv + iB.y;
        o1.z = (acc[i][6]+bz[6])*sv + iB.z; o1.w = (acc[i][7]+bz[7])*sv + iB.w;
        *(float4*)(out + m * C_ + n)     = o0;
        *(float4*)(out + m * C_ + n + 4) = o1;
    }
}

// =====================================================================
extern "C" void kernel_launch(void* const* d_in, const int* in_sizes, int n_in,
                              void* d_out, int out_size) {
    const float* inputs = (const float*)d_in[0];
    const float* bn1_g  = (const float*)d_in[1];
    const float* bn1_b  = (const float*)d_in[2];
    const float* bn1_m  = (const float*)d_in[3];
    const float* bn1_v  = (const float*)d_in[4];
    const float* bn2_g  = (const float*)d_in[5];
    const float* bn2_b  = (const float*)d_in[6];
    const float* bn2_m  = (const float*)d_in[7];
    const float* bn2_v  = (const float*)d_in[8];
    const float* W_g    = (const float*)d_in[9];
    const float* b_g    = (const float*)d_in[10];
    const float* W_th   = (const float*)d_in[11];
    const float* b_th   = (const float*)d_in[12];
    const float* W_ph   = (const float*)d_in[13];
    const float* b_ph   = (const float*)d_in[14];
    const float* W_z    = (const float*)d_in[15];
    const float* b_z    = (const float*)d_in[16];
    const float* sita   = (const float*)d_in[17];
    float* out = (float*)d_out;

    // K1: bn1 + elu
    bn1_elu_kernel<<<(M_*C_/4)/256, 256>>>(inputs, bn1_g, bn1_b, bn1_m, bn1_v);

    // K2: three projections in one launch (y: 0=theta, 1=g pooled, 2=phi pooled)
    proj_gemm_kernel<<<dim3(M_/128, 3), 256>>>(W_th, b_th, W_g, b_g, W_ph, b_ph);

    // K3: flash attention
    cudaFuncSetAttribute(attn_kernel,
                         cudaFuncAttributeMaxDynamicSharedMemorySize,
                         ATT_SMEM_BYTES);
    attn_kernel<<<dim3(NQ_/64, B_), 256, ATT_SMEM_BYTES>>>();

    // K4: final GEMM + bn2/elu + residual
    final_gemm_kernel<<<dim3(M_/128, C_/128), 256>>>(
        W_z, b_z, bn2_g, bn2_b, bn2_m, bn2_v, sita, inputs, out);
}

// round 13
// speedup vs baseline: 3.3260x; 3.3260x over previous
#include <cuda_runtime.h>
#include <cuda_bf16.h>
#include <math.h>
#include <stdint.h>

#define B_   8
#define H_   64
#define W_   64
#define C_   256
#define CI_  128
#define NQ_  (H_*W_)        // 4096
#define NS_  (H_*(W_/2))    // 2048
#define M_   (B_*NQ_)       // 32768
#define MS_  (B_*NS_)       // 16384
#define EPS_ 1e-3f

// ---- scratch (static __device__ — allocation-free per harness rules) ----
__device__ float d_x[M_*(size_t)C_];               // elu(bn1(inputs))
__device__ float d_y[M_*(size_t)CI_];              // attention output
__device__ __nv_bfloat16 d_th_hi[M_*(size_t)CI_];  // theta hi
__device__ __nv_bfloat16 d_th_lo[M_*(size_t)CI_];  // theta lo
__device__ __nv_bfloat16 d_ph_hi[MS_*(size_t)CI_]; // pooled phi hi
__device__ __nv_bfloat16 d_ph_lo[MS_*(size_t)CI_];
__device__ __nv_bfloat16 d_gT_hi[(size_t)B_*CI_*NS_]; // pooled g transposed [B][Ci][Ns]
__device__ __nv_bfloat16 d_gT_lo[(size_t)B_*CI_*NS_];

// ======================= warp-MMA helpers (non-'a' PTX, sm_80+) ======
__device__ __forceinline__ uint32_t smem_u32(const void* p){
    uint32_t a;
    asm("{ .reg .u64 t; cvta.to.shared.u64 t, %1; cvt.u32.u64 %0, t; }"
        : "=r"(a) : "l"(p));
    return a;
}
__device__ __forceinline__ void ldsm4(uint32_t* r, uint32_t a){
    asm volatile("ldmatrix.sync.aligned.m8n8.x4.shared.b16 {%0,%1,%2,%3}, [%4];"
        : "=r"(r[0]), "=r"(r[1]), "=r"(r[2]), "=r"(r[3]) : "r"(a));
}
__device__ __forceinline__ void ldsm2(uint32_t* r, uint32_t a){
    asm volatile("ldmatrix.sync.aligned.m8n8.x2.shared.b16 {%0,%1}, [%2];"
        : "=r"(r[0]), "=r"(r[1]) : "r"(a));
}
__device__ __forceinline__ void mma16816(float* c, const uint32_t* a, const uint32_t* b){
    asm volatile("mma.sync.aligned.m16n8k16.row.col.f32.bf16.bf16.f32 "
        "{%0,%1,%2,%3}, {%4,%5,%6,%7}, {%8,%9}, {%0,%1,%2,%3};"
        : "+f"(c[0]), "+f"(c[1]), "+f"(c[2]), "+f"(c[3])
        : "r"(a[0]), "r"(a[1]), "r"(a[2]), "r"(a[3]), "r"(b[0]), "r"(b[1]));
}
__device__ __forceinline__ uint32_t pack_hilo(float x, float y, uint32_t& lo){
    __nv_bfloat162 h;
    h.x = __float2bfloat16(x); h.y = __float2bfloat16(y);
    __nv_bfloat162 l;
    l.x = __float2bfloat16(x - __bfloat162float(h.x));
    l.y = __float2bfloat16(y - __bfloat162float(h.y));
    lo = *(uint32_t*)&l;
    return *(uint32_t*)&h;
}

// =====================================================================
// K1: x = elu(bn1(inputs))
// =====================================================================
__global__ void bn1_elu_kernel(const float* __restrict__ in,
                               const float* __restrict__ gamma,
                               const float* __restrict__ beta,
                               const float* __restrict__ mean,
                               const float* __restrict__ var) {
    int i = blockIdx.x * blockDim.x + threadIdx.x;
    int c0 = (i & (C_/4 - 1)) * 4;
    float4 v = ((const float4*)in)[i];
    float r[4] = {v.x, v.y, v.z, v.w};
#pragma unroll
    for (int j = 0; j < 4; j++) {
        int c = c0 + j;
        float sc = gamma[c] * rsqrtf(var[c] + EPS_);
        float t = (r[j] - mean[c]) * sc + beta[c];
        r[j] = t > 0.f ? t : expm1f(t);
    }
    ((float4*)d_x)[i] = make_float4(r[0], r[1], r[2], r[3]);
}

// =====================================================================
// K2: projection GEMM + bf16 hi/lo split epilogue
//     blockIdx.y: 0=theta (plain), 1=g (pooled, transposed), 2=phi (pooled)
// =====================================================================
__global__ void __launch_bounds__(256) proj_gemm_kernel(
        const float* __restrict__ W0, const float* __restrict__ b0,
        const float* __restrict__ W1, const float* __restrict__ b1,
        const float* __restrict__ W2, const float* __restrict__ b2) {
    __shared__ float As[16][132];
    __shared__ float Bs[16][132];
    const int which = blockIdx.y;
    const float* Wt   = (which == 0) ? W0 : (which == 1) ? W1 : W2;
    const float* bias = (which == 0) ? b0 : (which == 1) ? b1 : b2;
    const int bm = blockIdx.x * 128;
    const int t = threadIdx.x;
    const int tm = t >> 4, tn = t & 15;
    float acc[8][8] = {};

    for (int k0 = 0; k0 < C_; k0 += 16) {
#pragma unroll
        for (int r = 0; r < 2; r++) {
            int idx = t + r * 256;
            int row = idx >> 2;
            int kk  = (idx & 3) << 2;
            float4 v = *(const float4*)(d_x + (size_t)(bm + row) * C_ + k0 + kk);
            As[kk+0][row] = v.x; As[kk+1][row] = v.y;
            As[kk+2][row] = v.z; As[kk+3][row] = v.w;
            int kk2 = idx >> 5;
            int nn  = (idx & 31) << 2;
            *(float4*)&Bs[kk2][nn] =
                *(const float4*)(Wt + (size_t)(k0 + kk2) * CI_ + nn);
        }
        __syncthreads();
#pragma unroll
        for (int k = 0; k < 16; k++) {
            float a[8], bb[8];
            *(float4*)(a)    = *(float4*)&As[k][tm*8];
            *(float4*)(a+4)  = *(float4*)&As[k][tm*8+4];
            *(float4*)(bb)   = *(float4*)&Bs[k][tn*8];
            *(float4*)(bb+4) = *(float4*)&Bs[k][tn*8+4];
#pragma unroll
            for (int i = 0; i < 8; i++)
#pragma unroll
                for (int j = 0; j < 8; j++) acc[i][j] += a[i] * bb[j];
        }
        __syncthreads();
    }

    float bz[8];
#pragma unroll
    for (int j = 0; j < 8; j++) bz[j] = bias[tn*8 + j];

    if (which == 0) {
#pragma unroll
        for (int i = 0; i < 8; i++) {
            size_t m = bm + tm*8 + i;
            __align__(16) __nv_bfloat16 hb[8], lb[8];
#pragma unroll
            for (int j = 0; j < 8; j++) {
                float v = acc[i][j] + bz[j];
                hb[j] = __float2bfloat16(v);
                lb[j] = __float2bfloat16(v - __bfloat162float(hb[j]));
            }
            *(uint4*)(d_th_hi + m*CI_ + tn*8) = *(uint4*)hb;
            *(uint4*)(d_th_lo + m*CI_ + tn*8) = *(uint4*)lb;
        }
    } else if (which == 2) {
#pragma unroll
        for (int i = 0; i < 8; i += 2) {
            size_t pm = (size_t)(bm + tm*8 + i) >> 1;
            __align__(16) __nv_bfloat16 hb[8], lb[8];
#pragma unroll
            for (int j = 0; j < 8; j++) {
                float v = fmaxf(acc[i][j], acc[i+1][j]) + bz[j];
                hb[j] = __float2bfloat16(v);
                lb[j] = __float2bfloat16(v - __bfloat162float(hb[j]));
            }
            *(uint4*)(d_ph_hi + pm*CI_ + tn*8) = *(uint4*)hb;
            *(uint4*)(d_ph_lo + pm*CI_ + tn*8) = *(uint4*)lb;
        }
    } else {
        // g: pooled + transposed [B][Ci][Ns] hi/lo
        size_t pm0 = (size_t)(bm + tm*8) >> 1;
        int bb_ = (int)(pm0 >> 11);
        int key0 = (int)(pm0 & 2047);
#pragma unroll
        for (int j = 0; j < 8; j++) {
            int c = tn*8 + j;
            __align__(8) __nv_bfloat16 hq[4], lq[4];
#pragma unroll
            for (int i2 = 0; i2 < 4; i2++) {
                float v = fmaxf(acc[2*i2][j], acc[2*i2+1][j]) + bz[j];
                hq[i2] = __float2bfloat16(v);
                lq[i2] = __float2bfloat16(v - __bfloat162float(hq[i2]));
            }
            size_t off = ((size_t)bb_*CI_ + c)*NS_ + key0;
            *(uint2*)(d_gT_hi + off) = *(uint2*)hq;
            *(uint2*)(d_gT_lo + off) = *(uint2*)lq;
        }
    }
}

// =====================================================================
// K3: warp-MMA attention (mma.sync bf16, 3-term hi/lo split).
//     CTA: 128 q x 2048 keys. 8 warps x 16 q-rows. No-max softmax
//     (logits bounded), P kept in registers (C-frag == A-frag layout),
//     O accumulated in fp32 registers across all 16 key blocks.
// =====================================================================
#define RS_ 136                      // smem row stride in bf16 (272 B)
#define ATT_SMEM (6*128*RS_*2)       // 208896 B

__global__ void __launch_bounds__(256, 1) attn_mma_kernel() {
    extern __shared__ __nv_bfloat16 sm[];
    __nv_bfloat16* sThH = sm;
    __nv_bfloat16* sThL = sm + 1*128*RS_;
    __nv_bfloat16* sPhH = sm + 2*128*RS_;
    __nv_bfloat16* sPhL = sm + 3*128*RS_;
    __nv_bfloat16* sGH  = sm + 4*128*RS_;
    __nv_bfloat16* sGL  = sm + 5*128*RS_;

    const int t = threadIdx.x, wid = t >> 5, lane = t & 31;
    const int b = blockIdx.y, q0 = blockIdx.x * 128;
    const int wq = wid * 16;
    const int gid = lane >> 2, tig = lane & 3;

    // prologue: theta tile hi/lo -> smem
    {
        const __nv_bfloat16* thH = d_th_hi + ((size_t)b*NQ_ + q0)*CI_;
        const __nv_bfloat16* thL = d_th_lo + ((size_t)b*NQ_ + q0)*CI_;
#pragma unroll
        for (int u = 0; u < 8; u++) {
            int idx = u*256 + t, row = idx >> 4, c16 = idx & 15;
            *(uint4*)&sThH[row*RS_ + c16*8] = *(const uint4*)(thH + (size_t)row*CI_ + c16*8);
            *(uint4*)&sThL[row*RS_ + c16*8] = *(const uint4*)(thL + (size_t)row*CI_ + c16*8);
        }
    }

    float oc[16][4];
#pragma unroll
    for (int n = 0; n < 16; n++) { oc[n][0]=oc[n][1]=oc[n][2]=oc[n][3]=0.f; }
    float ls0 = 0.f, ls1 = 0.f;

    // ldmatrix base addresses (byte offsets added per k-chunk / n-tile)
    const int arow  = wq + (lane & 15);
    const int acol8 = ((lane >> 4) & 1) * 8;
    const uint32_t aThH = smem_u32(&sThH[arow*RS_ + acol8]);
    const uint32_t aThL = smem_u32(&sThL[arow*RS_ + acol8]);
    const int brow = lane & 7;
    const int bk8  = ((lane >> 3) & 1) * 8;
    const uint32_t bPhH = smem_u32(&sPhH[brow*RS_ + bk8]);
    const uint32_t bPhL = smem_u32(&sPhL[brow*RS_ + bk8]);
    const uint32_t bGH  = smem_u32(&sGH [brow*RS_ + bk8]);
    const uint32_t bGL  = smem_u32(&sGL [brow*RS_ + bk8]);

    for (int blk = 0; blk < 16; blk++) {
        // load phi hi/lo + gT hi/lo chunk
        {
            const __nv_bfloat16* phH = d_ph_hi + ((size_t)b*NS_ + blk*128)*CI_;
            const __nv_bfloat16* phL = d_ph_lo + ((size_t)b*NS_ + blk*128)*CI_;
            const __nv_bfloat16* gH  = d_gT_hi + (size_t)b*CI_*NS_ + blk*128;
            const __nv_bfloat16* gL  = d_gT_lo + (size_t)b*CI_*NS_ + blk*128;
#pragma unroll
            for (int u = 0; u < 8; u++) {
                int idx = u*256 + t, row = idx >> 4, c16 = idx & 15;
                *(uint4*)&sPhH[row*RS_ + c16*8] = *(const uint4*)(phH + (size_t)row*CI_ + c16*8);
                *(uint4*)&sPhL[row*RS_ + c16*8] = *(const uint4*)(phL + (size_t)row*CI_ + c16*8);
                *(uint4*)&sGH [row*RS_ + c16*8] = *(const uint4*)(gH  + (size_t)row*NS_ + c16*8);
                *(uint4*)&sGL [row*RS_ + c16*8] = *(const uint4*)(gL  + (size_t)row*NS_ + c16*8);
            }
        }
        __syncthreads();

        // S = theta . phi^T  (16 q-rows x 128 keys per warp, 3-term split)
        float sc[16][4];
#pragma unroll
        for (int n = 0; n < 16; n++) { sc[n][0]=sc[n][1]=sc[n][2]=sc[n][3]=0.f; }
#pragma unroll
        for (int kc = 0; kc < 8; kc++) {
            uint32_t ah[4], al[4];
            ldsm4(ah, aThH + kc*32);
            ldsm4(al, aThL + kc*32);
#pragma unroll
            for (int n = 0; n < 16; n++) {
                uint32_t bh[2], bl[2];
                ldsm2(bh, bPhH + n*2176 + kc*32);   // 8 rows * 272 B = 2176
                ldsm2(bl, bPhL + n*2176 + kc*32);
                mma16816(sc[n], ah, bh);
                mma16816(sc[n], ah, bl);
                mma16816(sc[n], al, bh);
            }
        }

        // softmax (no max-subtraction) + O += P . g
#pragma unroll
        for (int jc = 0; jc < 8; jc++) {
            float e0 = __expf(sc[2*jc][0]),   e1 = __expf(sc[2*jc][1]);
            float e2 = __expf(sc[2*jc][2]),   e3 = __expf(sc[2*jc][3]);
            float e4 = __expf(sc[2*jc+1][0]), e5 = __expf(sc[2*jc+1][1]);
            float e6 = __expf(sc[2*jc+1][2]), e7 = __expf(sc[2*jc+1][3]);
            ls0 += e0 + e1 + e4 + e5;
            ls1 += e2 + e3 + e6 + e7;
            uint32_t ph[4], pl[4];
            ph[0] = pack_hilo(e0, e1, pl[0]);
            ph[1] = pack_hilo(e2, e3, pl[1]);
            ph[2] = pack_hilo(e4, e5, pl[2]);
            ph[3] = pack_hilo(e6, e7, pl[3]);
#pragma unroll
            for (int n = 0; n < 16; n++) {
                uint32_t bh[2], bl[2];
                ldsm2(bh, bGH + n*2176 + jc*32);
                ldsm2(bl, bGL + n*2176 + jc*32);
                mma16816(oc[n], ph, bh);
                mma16816(oc[n], ph, bl);
                mma16816(oc[n], pl, bh);
            }
        }
        __syncthreads();
    }

    // reduce l across the 4 lanes sharing each q-row, normalize, store
    ls0 += __shfl_xor_sync(0xffffffffu, ls0, 1);
    ls0 += __shfl_xor_sync(0xffffffffu, ls0, 2);
    ls1 += __shfl_xor_sync(0xffffffffu, ls1, 1);
    ls1 += __shfl_xor_sync(0xffffffffu, ls1, 2);
    float li0 = 1.f / ls0, li1 = 1.f / ls1;

    float* dst0 = d_y + ((size_t)b*NQ_ + q0 + wq + gid)*CI_ + tig*2;
    float* dst1 = d_y + ((size_t)b*NQ_ + q0 + wq + gid + 8)*CI_ + tig*2;
#pragma unroll
    for (int n = 0; n < 16; n++) {
        *(float2*)(dst0 + n*8) = make_float2(oc[n][0]*li0, oc[n][1]*li0);
        *(float2*)(dst1 + n*8) = make_float2(oc[n][2]*li1, oc[n][3]*li1);
    }
}

// =====================================================================
// K4: out = (elu(bn2(y)) @ W_z + b_z) * sita + inputs
// =====================================================================
__global__ void __launch_bounds__(256) final_gemm_kernel(
        const float* __restrict__ Wz, const float* __restrict__ bzv,
        const float* __restrict__ g2, const float* __restrict__ b2,
        const float* __restrict__ m2, const float* __restrict__ v2,
        const float* __restrict__ sita, const float* __restrict__ inp,
        float* __restrict__ out) {
    __shared__ float As[16][132];
    __shared__ float Bs[16][132];
    __shared__ float bnS[CI_], bnB[CI_];
    const int t = threadIdx.x;
    if (t < CI_) {
        float sc = g2[t] * rsqrtf(v2[t] + EPS_);
        bnS[t] = sc;
        bnB[t] = b2[t] - m2[t] * sc;
    }
    __syncthreads();

    const int bm = blockIdx.x * 128;
    const int bn = blockIdx.y * 128;
    const int tm = t >> 4, tn = t & 15;
    float acc[8][8] = {};

    for (int k0 = 0; k0 < CI_; k0 += 16) {
#pragma unroll
        for (int r = 0; r < 2; r++) {
            int idx = t + r * 256;
            int row = idx >> 2;
            int kk  = (idx & 3) << 2;
            float4 v = *(const float4*)(d_y + (size_t)(bm + row) * CI_ + k0 + kk);
            float e[4] = {v.x, v.y, v.z, v.w};
#pragma unroll
            for (int j = 0; j < 4; j++) {
                int k = k0 + kk + j;
                float u = e[j] * bnS[k] + bnB[k];
                e[j] = u > 0.f ? u : expm1f(u);
            }
            As[kk+0][row] = e[0]; As[kk+1][row] = e[1];
            As[kk+2][row] = e[2]; As[kk+3][row] = e[3];
            int kk2 = idx >> 5;
            int nn  = (idx & 31) << 2;
            *(float4*)&Bs[kk2][nn] =
                *(const float4*)(Wz + (size_t)(k0 + kk2) * C_ + bn + nn);
        }
        __syncthreads();
#pragma unroll
        for (int k = 0; k < 16; k++) {
            float a[8], bb[8];
            *(float4*)(a)    = *(float4*)&As[k][tm*8];
            *(float4*)(a+4)  = *(float4*)&As[k][tm*8+4];
            *(float4*)(bb)   = *(float4*)&Bs[k][tn*8];
            *(float4*)(bb+4) = *(float4*)&Bs[k][tn*8+4];
#pragma unroll
            for (int i = 0; i < 8; i++)
#pragma unroll
                for (int j = 0; j < 8; j++) acc[i][j] += a[i] * bb[j];
        }
        __syncthreads();
    }

    const float sv = sita[0];
    float bz[8];
#pragma unroll
    for (int j = 0; j < 8; j++) bz[j] = bzv[bn + tn*8 + j];
#pragma unroll
    for (int i = 0; i < 8; i++) {
        size_t m = bm + tm*8 + i;
        size_t n = bn + tn*8;
        float4 iA = *(const float4*)(inp + m * C_ + n);
        float4 iB = *(const float4*)(inp + m * C_ + n + 4);
        float4 o0, o1;
        o0.x = (acc[i][0]+bz[0])*sv + iA.x; o0.y = (acc[i][1]+bz[1])*sv + iA.y;
        o0.z = (acc[i][2]+bz[2])*sv + iA.z; o0.w = (acc[i][3]+bz[3])*sv + iA.w;
        o1.x = (acc[i][4]+bz[4])*sv + iB.x; o1.y = (acc[i][5]+bz[5])*sv + iB.y;
        o1.z = (acc[i][6]+bz[6])*sv + iB.z; o1.w = (acc[i][7]+bz[7])*sv + iB.w;
        *(float4*)(out + m * C_ + n)     = o0;
        *(float4*)(out + m * C_ + n + 4) = o1;
    }
}

// =====================================================================
extern "C" void kernel_launch(void* const* d_in, const int* in_sizes, int n_in,
                              void* d_out, int out_size) {
    const float* inputs = (const float*)d_in[0];
    const float* bn1_g  = (const float*)d_in[1];
    const float* bn1_b  = (const float*)d_in[2];
    const float* bn1_m  = (const float*)d_in[3];
    const float* bn1_v  = (const float*)d_in[4];
    const float* bn2_g  = (const float*)d_in[5];
    const float* bn2_b  = (const float*)d_in[6];
    const float* bn2_m  = (const float*)d_in[7];
    const float* bn2_v  = (const float*)d_in[8];
    const float* W_g    = (const float*)d_in[9];
    const float* b_g    = (const float*)d_in[10];
    const float* W_th   = (const float*)d_in[11];
    const float* b_th   = (const float*)d_in[12];
    const float* W_ph   = (const float*)d_in[13];
    const float* b_ph   = (const float*)d_in[14];
    const float* W_z    = (const float*)d_in[15];
    const float* b_z    = (const float*)d_in[16];
    const float* sita   = (const float*)d_in[17];
    float* out = (float*)d_out;

    bn1_elu_kernel<<<(M_*C_/4)/256, 256>>>(inputs, bn1_g, bn1_b, bn1_m, bn1_v);

    proj_gemm_kernel<<<dim3(M_/128, 3), 256>>>(W_th, b_th, W_g, b_g, W_ph, b_ph);

    cudaFuncSetAttribute(attn_mma_kernel,
                         cudaFuncAttributeMaxDynamicSharedMemorySize, ATT_SMEM);
    attn_mma_kernel<<<dim3(NQ_/128, B_), 256, ATT_SMEM>>>();

    final_gemm_kernel<<<dim3(M_/128, C_/128), 256>>>(
        W_z, b_z, bn2_g, bn2_b, bn2_m, bn2_v, sita, inputs, out);
}